// round 5
// baseline (speedup 1.0000x reference)
#include <cuda_runtime.h>
#include <cuda_bf16.h>
#include <cstdint>

#define DIM    128
#define BATCH  1048576
#define NTILES (BATCH / DIM)   // 8192
#define GRID   152
#define PITCHB 272             // smem A row pitch in bytes (17 x 16B -> LDSM conflict-free)

// ---------------------------------------------------------------------------
// helpers
// ---------------------------------------------------------------------------
__device__ __forceinline__ uint32_t smem_u32(const void* p) {
    uint32_t a;
    asm("{ .reg .u64 t; cvta.to.shared.u64 t, %1; cvt.u32.u64 %0, t; }"
        : "=r"(a) : "l"(p));
    return a;
}

__device__ __forceinline__ unsigned short bfbits(__nv_bfloat16 h) {
    return *reinterpret_cast<unsigned short*>(&h);
}

// mma.sync m16n8k16 row.col f32.bf16.bf16.f32  (base PTX ISA, works at compute_103)
#define MMA16816(d, a, b)                                                        \
    asm volatile(                                                                \
        "mma.sync.aligned.m16n8k16.row.col.f32.bf16.bf16.f32 "                   \
        "{%0,%1,%2,%3}, {%4,%5,%6,%7}, {%8,%9}, {%0,%1,%2,%3};"                  \
        : "+f"((d)[0]), "+f"((d)[1]), "+f"((d)[2]), "+f"((d)[3])                 \
        : "r"((a)[0]), "r"((a)[1]), "r"((a)[2]), "r"((a)[3]),                    \
          "r"((b)[0]), "r"((b)[1]))

#define LDSM4(r, addr)                                                           \
    asm volatile("ldmatrix.sync.aligned.m8n8.x4.shared.b16 {%0,%1,%2,%3}, [%4];" \
                 : "=r"((r)[0]), "=r"((r)[1]), "=r"((r)[2]), "=r"((r)[3])        \
                 : "r"(addr))

// ---------------------------------------------------------------------------
// Global scratch: W = Q*diag*s split into bf16 hi/lo, row-major W[k][n]
// ---------------------------------------------------------------------------
__device__ __align__(16) __nv_bfloat16 g_Whi[DIM * DIM];
__device__ __align__(16) __nv_bfloat16 g_Wlo[DIM * DIM];

// ---------------------------------------------------------------------------
// Kernel 1: build Q via 128 sequential Householder reflections, emit W hi/lo
// 256 threads = 2 threads per Q row, 64 floats of the row in registers each.
// ---------------------------------------------------------------------------
__global__ void __launch_bounds__(256, 1)
build_w_kernel(const float* __restrict__ V, const float* __restrict__ scale,
               const float* __restrict__ diag, float* __restrict__ out,
               int out_size) {
    __shared__ float vraw[DIM];
    __shared__ float s_inv;

    int t    = threadIdx.x;   // 0..255
    int lane = t & 31;
    int r    = t >> 1;        // Q row 0..127
    int h    = t & 1;         // which 64-col half

    float q[64];
#pragma unroll
    for (int j = 0; j < 64; j++) q[j] = 0.0f;
    {
        int c0 = h * 64;
        if (r >= c0 && r < c0 + 64) q[r - c0] = 1.0f;   // identity
    }

    for (int i = 0; i < DIM; i++) {
        if (t < DIM) vraw[t] = V[t * DIM + i];          // column i of v_vectors
        __syncthreads();
        if (t < 32) {
            float ss = vraw[lane] * vraw[lane] + vraw[lane + 32] * vraw[lane + 32] +
                       vraw[lane + 64] * vraw[lane + 64] + vraw[lane + 96] * vraw[lane + 96];
#pragma unroll
            for (int o = 16; o; o >>= 1) ss += __shfl_xor_sync(0xffffffffu, ss, o);
            if (lane == 0) s_inv = 1.0f / (sqrtf(ss) + 1e-8f);
        }
        __syncthreads();
        float inv = s_inv;
        const float4* vb = (const float4*)(vraw + h * 64);
        float dp = 0.0f;
#pragma unroll
        for (int j4 = 0; j4 < 16; j4++) {
            float4 v4 = vb[j4];
            dp += q[4 * j4 + 0] * v4.x;
            dp += q[4 * j4 + 1] * v4.y;
            dp += q[4 * j4 + 2] * v4.z;
            dp += q[4 * j4 + 3] * v4.w;
        }
        dp += __shfl_xor_sync(0xffffffffu, dp, 1);      // combine both halves of row
        float coef = 2.0f * inv * inv * dp;             // Q -= 2 (Q v̂) v̂ᵀ
#pragma unroll
        for (int j4 = 0; j4 < 16; j4++) {
            float4 v4 = vb[j4];
            q[4 * j4 + 0] -= coef * v4.x;
            q[4 * j4 + 1] -= coef * v4.y;
            q[4 * j4 + 2] -= coef * v4.z;
            q[4 * j4 + 3] -= coef * v4.w;
        }
        __syncthreads();
    }

    // W[r][c] = Q[r][c] * diag[c] * s, split into bf16 hi+lo, row-major
    float s = scale[0];
#pragma unroll
    for (int j = 0; j < 64; j++) {
        int c = h * 64 + j;
        float w = q[j] * diag[c] * s;
        __nv_bfloat16 hi = __float2bfloat16(w);
        float lof = w - __bfloat162float(hi);
        g_Whi[r * DIM + c] = hi;
        g_Wlo[r * DIM + c] = __float2bfloat16(lof);
    }

    if (t == 0 && out_size > BATCH * DIM) {
        float ld = 0.0f;
        for (int c = 0; c < DIM; c++) ld += logf(fabsf(diag[c] * s) + 1e-8f);
        out[(size_t)BATCH * DIM] = ld;
    }
}

// ---------------------------------------------------------------------------
// Kernel 2: y = x @ W via mma.sync bf16 split (hi*hi + hi*lo + lo*hi).
// Persistent CTAs (152), 256 thr = 8 warps. Each warp owns 16 N-columns,
// holds its W fragments (hi+lo) entirely in registers. A is staged per tile
// through smem (bf16 hi/lo, 272B pitch). Next tile's LDGs issued before the
// compute loop so memory overlaps HMMA.
// ---------------------------------------------------------------------------
#define SMEM_BYTES (2 * 128 * PITCHB)   // 69632

__global__ void __launch_bounds__(256, 1)
gemm_kernel(const float* __restrict__ x, float* __restrict__ y) {
    extern __shared__ char sm[];
    char* smAhi = sm;
    char* smAlo = sm + 128 * PITCHB;
    uint32_t sbHi = smem_u32(smAhi);
    uint32_t sbLo = smem_u32(smAlo);

    int t = threadIdx.x, wid = t >> 5, lane = t & 31;
    int g = lane >> 2, tid4 = lane & 3;
    int warpN = wid * 16;

    // ---- W fragments into registers (once per warp) ----
    uint32_t Bh[8][2][2], Bl[8][2][2];
#pragma unroll
    for (int ks = 0; ks < 8; ks++) {
#pragma unroll
        for (int sl = 0; sl < 2; sl++) {
            int n  = warpN + sl * 8 + g;
            int k0 = ks * 16 + tid4 * 2;
            Bh[ks][sl][0] = (uint32_t)bfbits(g_Whi[k0 * DIM + n]) |
                            ((uint32_t)bfbits(g_Whi[(k0 + 1) * DIM + n]) << 16);
            Bh[ks][sl][1] = (uint32_t)bfbits(g_Whi[(k0 + 8) * DIM + n]) |
                            ((uint32_t)bfbits(g_Whi[(k0 + 9) * DIM + n]) << 16);
            Bl[ks][sl][0] = (uint32_t)bfbits(g_Wlo[k0 * DIM + n]) |
                            ((uint32_t)bfbits(g_Wlo[(k0 + 1) * DIM + n]) << 16);
            Bl[ks][sl][1] = (uint32_t)bfbits(g_Wlo[(k0 + 8) * DIM + n]) |
                            ((uint32_t)bfbits(g_Wlo[(k0 + 9) * DIM + n]) << 16);
        }
    }

    // ldmatrix source address for this lane (row = lane&15, col8 = lane>>4)
    uint32_t lrow = (uint32_t)(lane & 15);
    uint32_t lcol = (uint32_t)((lane >> 4) << 3);

    int tile = blockIdx.x;
    if (tile >= NTILES) return;

    // ---- preload tile 0: 16 float4 per thread ----
    float4 f[16];
    {
        const float4* xt4 = (const float4*)(x + (size_t)tile * DIM * DIM);
#pragma unroll
        for (int it = 0; it < 16; it++) f[it] = __ldcs(xt4 + it * 256 + t);
    }

    while (true) {
        int next = tile + GRID;

        __syncthreads();   // previous tile's smem readers are done

        // ---- convert f -> smem bf16 hi/lo (consumes f) ----
#pragma unroll
        for (int it = 0; it < 16; it++) {
            int idx = it * 256 + t;          // 0..4095 float4 chunks
            int row = idx >> 5, c5 = idx & 31;
            float4 v = f[it];
            __nv_bfloat16 h0 = __float2bfloat16(v.x);
            __nv_bfloat16 h1 = __float2bfloat16(v.y);
            __nv_bfloat16 h2 = __float2bfloat16(v.z);
            __nv_bfloat16 h3 = __float2bfloat16(v.w);
            __nv_bfloat16 l0 = __float2bfloat16(v.x - __bfloat162float(h0));
            __nv_bfloat16 l1 = __float2bfloat16(v.y - __bfloat162float(h1));
            __nv_bfloat16 l2 = __float2bfloat16(v.z - __bfloat162float(h2));
            __nv_bfloat16 l3 = __float2bfloat16(v.w - __bfloat162float(h3));
            uint2 hv, lv;
            hv.x = (uint32_t)bfbits(h0) | ((uint32_t)bfbits(h1) << 16);
            hv.y = (uint32_t)bfbits(h2) | ((uint32_t)bfbits(h3) << 16);
            lv.x = (uint32_t)bfbits(l0) | ((uint32_t)bfbits(l1) << 16);
            lv.y = (uint32_t)bfbits(l2) | ((uint32_t)bfbits(l3) << 16);
            *(uint2*)(smAhi + row * PITCHB + c5 * 8) = hv;
            *(uint2*)(smAlo + row * PITCHB + c5 * 8) = lv;
        }
        __syncthreads();

        // ---- issue next tile's LDGs now (consumed next iteration) ----
        if (next < NTILES) {
            const float4* xt4 = (const float4*)(x + (size_t)next * DIM * DIM);
#pragma unroll
            for (int it = 0; it < 16; it++) f[it] = __ldcs(xt4 + it * 256 + t);
        }

        // ---- compute + store this tile ----
        float* yt = y + (size_t)tile * DIM * DIM;
#pragma unroll
        for (int mb = 0; mb < 8; mb++) {
            float acc[2][2][4];   // [n8-slice][ks-parity][4]
#pragma unroll
            for (int sl = 0; sl < 2; sl++)
#pragma unroll
                for (int p = 0; p < 2; p++)
#pragma unroll
                    for (int i = 0; i < 4; i++) acc[sl][p][i] = 0.0f;

#pragma unroll
            for (int ks = 0; ks < 8; ks++) {
                uint32_t off = (uint32_t)(mb * 16 + lrow) * PITCHB +
                               (uint32_t)(ks * 16 + lcol) * 2;
                uint32_t Ah[4], Al[4];
                LDSM4(Ah, sbHi + off);
                LDSM4(Al, sbLo + off);
                int p = ks & 1;
#pragma unroll
                for (int sl = 0; sl < 2; sl++) {
                    MMA16816(acc[sl][p], Ah, Bh[ks][sl]);
                    MMA16816(acc[sl][p], Ah, Bl[ks][sl]);
                    MMA16816(acc[sl][p], Al, Bh[ks][sl]);
                }
            }

            int row0 = mb * 16 + g;
#pragma unroll
            for (int sl = 0; sl < 2; sl++) {
                int cb = warpN + sl * 8 + tid4 * 2;
                float2 v0, v1;
                v0.x = acc[sl][0][0] + acc[sl][1][0];
                v0.y = acc[sl][0][1] + acc[sl][1][1];
                v1.x = acc[sl][0][2] + acc[sl][1][2];
                v1.y = acc[sl][0][3] + acc[sl][1][3];
                __stcs((float2*)(yt + (size_t)row0 * DIM + cb), v0);
                __stcs((float2*)(yt + (size_t)(row0 + 8) * DIM + cb), v1);
            }
        }

        tile = next;
        if (tile >= NTILES) break;
    }
}

// ---------------------------------------------------------------------------
// Launch
// ---------------------------------------------------------------------------
extern "C" void kernel_launch(void* const* d_in, const int* in_sizes, int n_in,
                              void* d_out, int out_size) {
    const float* x    = (const float*)d_in[0];   // [BATCH, DIM]
    const float* V    = (const float*)d_in[1];   // [DIM, DIM] (v_i = columns)
    const float* sc   = (const float*)d_in[2];   // [1]
    const float* diag = (const float*)d_in[3];   // [DIM]
    float* out = (float*)d_out;

    build_w_kernel<<<1, 256>>>(V, sc, diag, out, out_size);

    static int smem_set = 0;
    if (!smem_set) {
        cudaFuncSetAttribute(gemm_kernel,
                             cudaFuncAttributeMaxDynamicSharedMemorySize, SMEM_BYTES);
        smem_set = 1;
    }
    gemm_kernel<<<GRID, 256, SMEM_BYTES>>>(x, out);
}

// round 7
// speedup vs baseline: 1.5748x; 1.5748x over previous
#include <cuda_runtime.h>
#include <cuda_bf16.h>
#include <cstdint>

#define DIM    128
#define BATCH  1048576
#define NTILES (BATCH / DIM)   // 8192
#define GRID   152
#define PITCHB 272             // bf16 A smem row pitch (17 x 16B -> LDSM conflict-free)

// ---------------------------------------------------------------------------
// helpers
// ---------------------------------------------------------------------------
__device__ __forceinline__ uint32_t smem_u32(const void* p) {
    uint32_t a;
    asm("{ .reg .u64 t; cvta.to.shared.u64 t, %1; cvt.u32.u64 %0, t; }"
        : "=r"(a) : "l"(p));
    return a;
}

__device__ __forceinline__ unsigned short bfbits(__nv_bfloat16 h) {
    return *reinterpret_cast<unsigned short*>(&h);
}

#define MMA16816(d, a, b)                                                        \
    asm volatile(                                                                \
        "mma.sync.aligned.m16n8k16.row.col.f32.bf16.bf16.f32 "                   \
        "{%0,%1,%2,%3}, {%4,%5,%6,%7}, {%8,%9}, {%0,%1,%2,%3};"                  \
        : "+f"((d)[0]), "+f"((d)[1]), "+f"((d)[2]), "+f"((d)[3])                 \
        : "r"((a)[0]), "r"((a)[1]), "r"((a)[2]), "r"((a)[3]),                    \
          "r"((b)[0]), "r"((b)[1]))

#define LDSM4(r, addr)                                                           \
    asm volatile("ldmatrix.sync.aligned.m8n8.x4.shared.b16 {%0,%1,%2,%3}, [%4];" \
                 : "=r"((r)[0]), "=r"((r)[1]), "=r"((r)[2]), "=r"((r)[3])        \
                 : "r"(addr))

#define CP_ASYNC16(smem_addr, gptr)                                              \
    asm volatile("cp.async.cg.shared.global [%0], [%1], 16;"                     \
                 :: "r"(smem_addr), "l"(gptr))
#define CP_COMMIT() asm volatile("cp.async.commit_group;")
#define CP_WAIT0()  asm volatile("cp.async.wait_group 0;")

// ---------------------------------------------------------------------------
// Global scratch: W = Q*diag*s split into bf16 hi/lo, row-major W[k][n]
// ---------------------------------------------------------------------------
__device__ __align__(16) __nv_bfloat16 g_Whi[DIM * DIM];
__device__ __align__(16) __nv_bfloat16 g_Wlo[DIM * DIM];

// ---------------------------------------------------------------------------
// Kernel 1: build Q via 128 sequential Householder reflections.
// V preloaded into smem transposed (column-contiguous), all inverse norms
// precomputed and folded into v-hat; the sequential loop is sync-free:
// each Q row is owned by a thread pair, combined with one shfl.
// VPITCH must keep columns 16B-aligned for float4 reads (132*4 = 528 = 33*16).
// ---------------------------------------------------------------------------
#define VPITCH 132
#define BW_SMEM (DIM * VPITCH * 4)   // 67584

__global__ void __launch_bounds__(256, 1)
build_w_kernel(const float* __restrict__ V, const float* __restrict__ scale,
               const float* __restrict__ diag, float* __restrict__ out,
               int out_size) {
    extern __shared__ float sv[];        // sv[col * VPITCH + row] = vhat
    __shared__ float s_invn[DIM];

    int t    = threadIdx.x;   // 0..255
    int r    = t >> 1;        // Q row 0..127
    int h    = t & 1;         // which 64-col half of the row

    // ---- load V transposed into smem (coalesced reads) ----
#pragma unroll
    for (int it = 0; it < 64; it++) {
        int idx = it * 256 + t;               // 0..16383
        int row = idx >> 7, col = idx & 127;  // V[row][col], columns are v_i
        sv[col * VPITCH + row] = V[idx];
    }
    __syncthreads();

    // ---- precompute 1/(||v_i|| + eps) ----
    if (t < DIM) {
        float ss = 0.0f;
        const float* c = sv + t * VPITCH;
#pragma unroll 8
        for (int j = 0; j < DIM; j++) ss += c[j] * c[j];
        s_invn[t] = 1.0f / (sqrtf(ss) + 1e-8f);
    }
    __syncthreads();

    // ---- normalize columns in place ----
#pragma unroll
    for (int it = 0; it < 64; it++) {
        int idx = it * 256 + t;
        int row = idx & 127, col = idx >> 7;
        sv[col * VPITCH + row] *= s_invn[col];
    }
    __syncthreads();

    // ---- Q rows in registers: 2 threads/row x 64 floats ----
    float q[64];
#pragma unroll
    for (int j = 0; j < 64; j++) q[j] = 0.0f;
    {
        int c0 = h * 64;
        if (r >= c0 && r < c0 + 64) q[r - c0] = 1.0f;
    }

    // ---- sequential reflections, no block syncs ----
    for (int i = 0; i < DIM; i++) {
        const float4* vb = (const float4*)(sv + i * VPITCH + h * 64);
        float4 v4[16];
#pragma unroll
        for (int j4 = 0; j4 < 16; j4++) v4[j4] = vb[j4];

        float d0 = 0.f, d1 = 0.f, d2 = 0.f, d3 = 0.f;
#pragma unroll
        for (int j4 = 0; j4 < 16; j4++) {
            d0 += q[4 * j4 + 0] * v4[j4].x;
            d1 += q[4 * j4 + 1] * v4[j4].y;
            d2 += q[4 * j4 + 2] * v4[j4].z;
            d3 += q[4 * j4 + 3] * v4[j4].w;
        }
        float dp = (d0 + d1) + (d2 + d3);
        dp += __shfl_xor_sync(0xffffffffu, dp, 1);   // combine row halves
        float coef = 2.0f * dp;                       // Q -= 2 (Q v^) v^T
#pragma unroll
        for (int j4 = 0; j4 < 16; j4++) {
            q[4 * j4 + 0] -= coef * v4[j4].x;
            q[4 * j4 + 1] -= coef * v4[j4].y;
            q[4 * j4 + 2] -= coef * v4[j4].z;
            q[4 * j4 + 3] -= coef * v4[j4].w;
        }
    }

    // ---- W[r][c] = Q[r][c]*diag[c]*s, split bf16 hi+lo ----
    float s = scale[0];
#pragma unroll
    for (int j = 0; j < 64; j++) {
        int c = h * 64 + j;
        float w = q[j] * diag[c] * s;
        __nv_bfloat16 hi = __float2bfloat16(w);
        float lof = w - __bfloat162float(hi);
        g_Whi[r * DIM + c] = hi;
        g_Wlo[r * DIM + c] = __float2bfloat16(lof);
    }

    if (t == 0 && out_size > BATCH * DIM) {
        float ld = 0.0f;
        for (int c = 0; c < DIM; c++) ld += logf(fabsf(diag[c] * s) + 1e-8f);
        out[(size_t)BATCH * DIM] = ld;
    }
}

// ---------------------------------------------------------------------------
// Kernel 2: y = x @ W, mma.sync bf16 split (hi*hi + hi*lo + lo*hi).
// Persistent 152 CTAs x 512 thr (16 warps, 8 N-cols each; W frags in regs).
// cp.async.cg stages the next fp32 x tile into smem while computing; each
// tile converted to bf16 hi/lo smem. 3 independent accumulator chains per
// warp kill the dependent-MMA stalls of R5.
// ---------------------------------------------------------------------------
#define SM_RAW 0                         // fp32 x tile: 128*128*4 = 65536
#define SM_AHI 65536                     // 128*272 = 34816
#define SM_ALO (65536 + 34816)
#define SMEM_BYTES (65536 + 2 * 34816)   // 135168

__global__ void __launch_bounds__(512, 1)
gemm_kernel(const float* __restrict__ x, float* __restrict__ y) {
    extern __shared__ char sm[];
    float* smRaw = (float*)(sm + SM_RAW);
    char*  smAhi = sm + SM_AHI;
    char*  smAlo = sm + SM_ALO;
    uint32_t sbRaw = smem_u32(smRaw);
    uint32_t sbHi  = smem_u32(smAhi);
    uint32_t sbLo  = smem_u32(smAlo);

    int t = threadIdx.x, wid = t >> 5, lane = t & 31;
    int g = lane >> 2, tid4 = lane & 3;
    int warpN = wid * 8;                  // 16 warps x 8 N-cols

    // ---- W fragments into registers (once) ----
    uint32_t Bh[8][2], Bl[8][2];
#pragma unroll
    for (int ks = 0; ks < 8; ks++) {
        int n  = warpN + g;
        int k0 = ks * 16 + tid4 * 2;
        Bh[ks][0] = (uint32_t)bfbits(g_Whi[k0 * DIM + n]) |
                    ((uint32_t)bfbits(g_Whi[(k0 + 1) * DIM + n]) << 16);
        Bh[ks][1] = (uint32_t)bfbits(g_Whi[(k0 + 8) * DIM + n]) |
                    ((uint32_t)bfbits(g_Whi[(k0 + 9) * DIM + n]) << 16);
        Bl[ks][0] = (uint32_t)bfbits(g_Wlo[k0 * DIM + n]) |
                    ((uint32_t)bfbits(g_Wlo[(k0 + 1) * DIM + n]) << 16);
        Bl[ks][1] = (uint32_t)bfbits(g_Wlo[(k0 + 8) * DIM + n]) |
                    ((uint32_t)bfbits(g_Wlo[(k0 + 9) * DIM + n]) << 16);
    }

    uint32_t lrow = (uint32_t)(lane & 15);
    uint32_t lcol = (uint32_t)((lane >> 4) << 3);

    int tile = blockIdx.x;
    if (tile >= NTILES) return;

    // ---- prologue: stage tile 0 ----
    {
        const float4* src = (const float4*)(x + (size_t)tile * DIM * DIM);
#pragma unroll
        for (int it = 0; it < 8; it++) {
            int idx = it * 512 + t;                 // 4096 x 16B chunks
            CP_ASYNC16(sbRaw + idx * 16, src + idx);
        }
        CP_COMMIT();
    }

    while (true) {
        CP_WAIT0();
        __syncthreads();       // raw ready AND all warps done with prev hi/lo

        // ---- convert raw fp32 -> bf16 hi/lo smem ----
#pragma unroll
        for (int it = 0; it < 8; it++) {
            int idx = it * 512 + t;
            int row = idx >> 5, c5 = idx & 31;
            float4 v = *(const float4*)(smRaw + (size_t)idx * 4);
            __nv_bfloat16 h0 = __float2bfloat16(v.x);
            __nv_bfloat16 h1 = __float2bfloat16(v.y);
            __nv_bfloat16 h2 = __float2bfloat16(v.z);
            __nv_bfloat16 h3 = __float2bfloat16(v.w);
            __nv_bfloat16 l0 = __float2bfloat16(v.x - __bfloat162float(h0));
            __nv_bfloat16 l1 = __float2bfloat16(v.y - __bfloat162float(h1));
            __nv_bfloat16 l2 = __float2bfloat16(v.z - __bfloat162float(h2));
            __nv_bfloat16 l3 = __float2bfloat16(v.w - __bfloat162float(h3));
            uint2 hv, lv;
            hv.x = (uint32_t)bfbits(h0) | ((uint32_t)bfbits(h1) << 16);
            hv.y = (uint32_t)bfbits(h2) | ((uint32_t)bfbits(h3) << 16);
            lv.x = (uint32_t)bfbits(l0) | ((uint32_t)bfbits(l1) << 16);
            lv.y = (uint32_t)bfbits(l2) | ((uint32_t)bfbits(l3) << 16);
            *(uint2*)(smAhi + row * PITCHB + c5 * 8) = hv;
            *(uint2*)(smAlo + row * PITCHB + c5 * 8) = lv;
        }
        __syncthreads();       // hi/lo ready; raw fully consumed

        // ---- stage next tile while computing this one ----
        int next = tile + GRID;
        if (next < NTILES) {
            const float4* src = (const float4*)(x + (size_t)next * DIM * DIM);
#pragma unroll
            for (int it = 0; it < 8; it++) {
                int idx = it * 512 + t;
                CP_ASYNC16(sbRaw + idx * 16, src + idx);
            }
            CP_COMMIT();
        }

        // ---- compute + store ----
        float* yt = y + (size_t)tile * DIM * DIM;
        for (int mb = 0; mb < 8; mb++) {
            float ahh[4] = {0.f, 0.f, 0.f, 0.f};
            float ahl[4] = {0.f, 0.f, 0.f, 0.f};
            float alh[4] = {0.f, 0.f, 0.f, 0.f};
#pragma unroll
            for (int ks = 0; ks < 8; ks++) {
                uint32_t off = (uint32_t)(mb * 16 + lrow) * PITCHB +
                               (uint32_t)(ks * 16 + lcol) * 2;
                uint32_t Ah[4], Al[4];
                LDSM4(Ah, sbHi + off);
                LDSM4(Al, sbLo + off);
                MMA16816(ahh, Ah, Bh[ks]);
                MMA16816(ahl, Ah, Bl[ks]);
                MMA16816(alh, Al, Bh[ks]);
            }
            int row0 = mb * 16 + g;
            int cb   = warpN + tid4 * 2;
            float2 v0, v1;
            v0.x = ahh[0] + ahl[0] + alh[0];
            v0.y = ahh[1] + ahl[1] + alh[1];
            v1.x = ahh[2] + ahl[2] + alh[2];
            v1.y = ahh[3] + ahl[3] + alh[3];
            __stcs((float2*)(yt + (size_t)row0 * DIM + cb), v0);
            __stcs((float2*)(yt + (size_t)(row0 + 8) * DIM + cb), v1);
        }

        tile = next;
        if (tile >= NTILES) break;
    }
}

// ---------------------------------------------------------------------------
// Launch
// ---------------------------------------------------------------------------
extern "C" void kernel_launch(void* const* d_in, const int* in_sizes, int n_in,
                              void* d_out, int out_size) {
    const float* x    = (const float*)d_in[0];   // [BATCH, DIM]
    const float* V    = (const float*)d_in[1];   // [DIM, DIM] (v_i = columns)
    const float* sc   = (const float*)d_in[2];   // [1]
    const float* diag = (const float*)d_in[3];   // [DIM]
    float* out = (float*)d_out;

    cudaFuncSetAttribute(build_w_kernel,
                         cudaFuncAttributeMaxDynamicSharedMemorySize, BW_SMEM);
    cudaFuncSetAttribute(gemm_kernel,
                         cudaFuncAttributeMaxDynamicSharedMemorySize, SMEM_BYTES);

    build_w_kernel<<<1, 256, BW_SMEM>>>(V, sc, diag, out, out_size);
    gemm_kernel<<<GRID, 512, SMEM_BYTES>>>(x, out);
}

// round 8
// speedup vs baseline: 1.8505x; 1.1751x over previous
#include <cuda_runtime.h>
#include <cuda_bf16.h>
#include <cstdint>

#define DIM    128
#define BATCH  1048576
#define NTILES (BATCH / DIM)   // 8192
#define GRID   152
#define PITCHB 272             // bf16 A smem row pitch (17 x 16B -> LDSM conflict-free)

// ---------------------------------------------------------------------------
// helpers
// ---------------------------------------------------------------------------
__device__ __forceinline__ uint32_t smem_u32(const void* p) {
    uint32_t a;
    asm("{ .reg .u64 t; cvta.to.shared.u64 t, %1; cvt.u32.u64 %0, t; }"
        : "=r"(a) : "l"(p));
    return a;
}

__device__ __forceinline__ unsigned short bfbits(__nv_bfloat16 h) {
    return *reinterpret_cast<unsigned short*>(&h);
}

#define MMA16816(d, a, b)                                                        \
    asm volatile(                                                                \
        "mma.sync.aligned.m16n8k16.row.col.f32.bf16.bf16.f32 "                   \
        "{%0,%1,%2,%3}, {%4,%5,%6,%7}, {%8,%9}, {%0,%1,%2,%3};"                  \
        : "+f"((d)[0]), "+f"((d)[1]), "+f"((d)[2]), "+f"((d)[3])                 \
        : "r"((a)[0]), "r"((a)[1]), "r"((a)[2]), "r"((a)[3]),                    \
          "r"((b)[0]), "r"((b)[1]))

#define LDSM4(r, addr)                                                           \
    asm volatile("ldmatrix.sync.aligned.m8n8.x4.shared.b16 {%0,%1,%2,%3}, [%4];" \
                 : "=r"((r)[0]), "=r"((r)[1]), "=r"((r)[2]), "=r"((r)[3])        \
                 : "r"(addr))

// ---------------------------------------------------------------------------
// Global scratch: W = Q*diag*s split into bf16 hi/lo, row-major W[k][n]
// ---------------------------------------------------------------------------
__device__ __align__(16) __nv_bfloat16 g_Whi[DIM * DIM];
__device__ __align__(16) __nv_bfloat16 g_Wlo[DIM * DIM];

// ---------------------------------------------------------------------------
// Kernel 1: build Q via 128 sequential Householder reflections.
// V preloaded into smem transposed (column-contiguous, 16B-aligned pitch),
// inverse norms folded into v-hat up front; the sequential loop is sync-free.
// ---------------------------------------------------------------------------
#define VPITCH 132
#define BW_SMEM (DIM * VPITCH * 4)   // 67584

__global__ void __launch_bounds__(256, 1)
build_w_kernel(const float* __restrict__ V, const float* __restrict__ scale,
               const float* __restrict__ diag, float* __restrict__ out,
               int out_size) {
    extern __shared__ float sv[];        // sv[col * VPITCH + row] = vhat
    __shared__ float s_invn[DIM];

    int t    = threadIdx.x;   // 0..255
    int r    = t >> 1;        // Q row 0..127
    int h    = t & 1;         // which 64-col half of the row

    // ---- load V transposed into smem (coalesced reads) ----
#pragma unroll
    for (int it = 0; it < 64; it++) {
        int idx = it * 256 + t;               // 0..16383
        int row = idx >> 7, col = idx & 127;  // V[row][col], columns are v_i
        sv[col * VPITCH + row] = V[idx];
    }
    __syncthreads();

    // ---- precompute 1/(||v_i|| + eps) ----
    if (t < DIM) {
        float ss = 0.0f;
        const float* c = sv + t * VPITCH;
#pragma unroll 8
        for (int j = 0; j < DIM; j++) ss += c[j] * c[j];
        s_invn[t] = 1.0f / (sqrtf(ss) + 1e-8f);
    }
    __syncthreads();

    // ---- normalize columns in place ----
#pragma unroll
    for (int it = 0; it < 64; it++) {
        int idx = it * 256 + t;
        int row = idx & 127, col = idx >> 7;
        sv[col * VPITCH + row] *= s_invn[col];
    }
    __syncthreads();

    // ---- Q rows in registers: 2 threads/row x 64 floats ----
    float q[64];
#pragma unroll
    for (int j = 0; j < 64; j++) q[j] = 0.0f;
    {
        int c0 = h * 64;
        if (r >= c0 && r < c0 + 64) q[r - c0] = 1.0f;
    }

    // ---- sequential reflections, no block syncs ----
    for (int i = 0; i < DIM; i++) {
        const float4* vb = (const float4*)(sv + i * VPITCH + h * 64);
        float4 v4[16];
#pragma unroll
        for (int j4 = 0; j4 < 16; j4++) v4[j4] = vb[j4];

        float d0 = 0.f, d1 = 0.f, d2 = 0.f, d3 = 0.f;
#pragma unroll
        for (int j4 = 0; j4 < 16; j4++) {
            d0 += q[4 * j4 + 0] * v4[j4].x;
            d1 += q[4 * j4 + 1] * v4[j4].y;
            d2 += q[4 * j4 + 2] * v4[j4].z;
            d3 += q[4 * j4 + 3] * v4[j4].w;
        }
        float dp = (d0 + d1) + (d2 + d3);
        dp += __shfl_xor_sync(0xffffffffu, dp, 1);   // combine row halves
        float coef = 2.0f * dp;                       // Q -= 2 (Q v^) v^T
#pragma unroll
        for (int j4 = 0; j4 < 16; j4++) {
            q[4 * j4 + 0] -= coef * v4[j4].x;
            q[4 * j4 + 1] -= coef * v4[j4].y;
            q[4 * j4 + 2] -= coef * v4[j4].z;
            q[4 * j4 + 3] -= coef * v4[j4].w;
        }
    }

    // ---- W[r][c] = Q[r][c]*diag[c]*s, split bf16 hi+lo ----
    float s = scale[0];
#pragma unroll
    for (int j = 0; j < 64; j++) {
        int c = h * 64 + j;
        float w = q[j] * diag[c] * s;
        __nv_bfloat16 hi = __float2bfloat16(w);
        float lof = w - __bfloat162float(hi);
        g_Whi[r * DIM + c] = hi;
        g_Wlo[r * DIM + c] = __float2bfloat16(lof);
    }

    if (t == 0 && out_size > BATCH * DIM) {
        float ld = 0.0f;
        for (int c = 0; c < DIM; c++) ld += logf(fabsf(diag[c] * s) + 1e-8f);
        out[(size_t)BATCH * DIM] = ld;
    }
}

// ---------------------------------------------------------------------------
// Kernel 2: y = x @ W, mma.sync bf16 split (hi*hi + hi*lo + lo*hi).
// Persistent 152 CTAs x 256 thr (8 warps). Each warp owns 16 N-columns
// (2 slices -> 6 MMAs per A-LDSM pair = 2x A smem reuse vs R7) and the full
// M range. W frags in regs (64). x prefetched straight into a register
// buffer (no raw smem round trip); converted to bf16 hi/lo smem per tile.
// ---------------------------------------------------------------------------
#define SM_AHI 0                         // 128*272 = 34816
#define SM_ALO 34816
#define SMEM_BYTES (2 * 34816)           // 69632

__global__ void __launch_bounds__(256, 1)
gemm_kernel(const float* __restrict__ x, float* __restrict__ y) {
    extern __shared__ char sm[];
    char* smAhi = sm + SM_AHI;
    char* smAlo = sm + SM_ALO;
    uint32_t sbHi = smem_u32(smAhi);
    uint32_t sbLo = smem_u32(smAlo);

    int t = threadIdx.x, wid = t >> 5, lane = t & 31;
    int g = lane >> 2, tid4 = lane & 3;
    int warpN = wid * 16;                 // 8 warps x 16 N-cols

    // ---- W fragments into registers (once): [ks][slice][2] ----
    uint32_t Bh[8][2][2], Bl[8][2][2];
#pragma unroll
    for (int ks = 0; ks < 8; ks++) {
#pragma unroll
        for (int sl = 0; sl < 2; sl++) {
            int n  = warpN + sl * 8 + g;
            int k0 = ks * 16 + tid4 * 2;
            Bh[ks][sl][0] = (uint32_t)bfbits(g_Whi[k0 * DIM + n]) |
                            ((uint32_t)bfbits(g_Whi[(k0 + 1) * DIM + n]) << 16);
            Bh[ks][sl][1] = (uint32_t)bfbits(g_Whi[(k0 + 8) * DIM + n]) |
                            ((uint32_t)bfbits(g_Whi[(k0 + 9) * DIM + n]) << 16);
            Bl[ks][sl][0] = (uint32_t)bfbits(g_Wlo[k0 * DIM + n]) |
                            ((uint32_t)bfbits(g_Wlo[(k0 + 1) * DIM + n]) << 16);
            Bl[ks][sl][1] = (uint32_t)bfbits(g_Wlo[(k0 + 8) * DIM + n]) |
                            ((uint32_t)bfbits(g_Wlo[(k0 + 9) * DIM + n]) << 16);
        }
    }

    uint32_t lrow = (uint32_t)(lane & 15);
    uint32_t lcol = (uint32_t)((lane >> 4) << 3);

    int tile = blockIdx.x;
    if (tile >= NTILES) return;

    // ---- preload tile 0 into register buffer (16 float4/thread) ----
    float4 f[16];
    {
        const float4* xt4 = (const float4*)(x + (size_t)tile * DIM * DIM);
#pragma unroll
        for (int it = 0; it < 16; it++) f[it] = __ldcs(xt4 + it * 256 + t);
    }

    while (true) {
        __syncthreads();   // prev tile's smem readers done

        // ---- convert f -> bf16 hi/lo smem (consumes f) ----
#pragma unroll
        for (int it = 0; it < 16; it++) {
            int idx = it * 256 + t;          // 0..4095 float4 chunks
            int row = idx >> 5, c5 = idx & 31;
            float4 v = f[it];
            __nv_bfloat16 h0 = __float2bfloat16(v.x);
            __nv_bfloat16 h1 = __float2bfloat16(v.y);
            __nv_bfloat16 h2 = __float2bfloat16(v.z);
            __nv_bfloat16 h3 = __float2bfloat16(v.w);
            __nv_bfloat16 l0 = __float2bfloat16(v.x - __bfloat162float(h0));
            __nv_bfloat16 l1 = __float2bfloat16(v.y - __bfloat162float(h1));
            __nv_bfloat16 l2 = __float2bfloat16(v.z - __bfloat162float(h2));
            __nv_bfloat16 l3 = __float2bfloat16(v.w - __bfloat162float(h3));
            uint2 hv, lv;
            hv.x = (uint32_t)bfbits(h0) | ((uint32_t)bfbits(h1) << 16);
            hv.y = (uint32_t)bfbits(h2) | ((uint32_t)bfbits(h3) << 16);
            lv.x = (uint32_t)bfbits(l0) | ((uint32_t)bfbits(l1) << 16);
            lv.y = (uint32_t)bfbits(l2) | ((uint32_t)bfbits(l3) << 16);
            *(uint2*)(smAhi + row * PITCHB + c5 * 8) = hv;
            *(uint2*)(smAlo + row * PITCHB + c5 * 8) = lv;
        }
        __syncthreads();   // hi/lo ready

        // ---- issue next tile's LDGs (consumed next iteration) ----
        int next = tile + GRID;
        if (next < NTILES) {
            const float4* xt4 = (const float4*)(x + (size_t)next * DIM * DIM);
#pragma unroll
            for (int it = 0; it < 16; it++) f[it] = __ldcs(xt4 + it * 256 + t);
        }

        // ---- compute + store this tile ----
        float* yt = y + (size_t)tile * DIM * DIM;
        for (int mb = 0; mb < 8; mb++) {
            float ahh[2][4], ahl[2][4], alh[2][4];
#pragma unroll
            for (int sl = 0; sl < 2; sl++)
#pragma unroll
                for (int i = 0; i < 4; i++) {
                    ahh[sl][i] = 0.f; ahl[sl][i] = 0.f; alh[sl][i] = 0.f;
                }
#pragma unroll
            for (int ks = 0; ks < 8; ks++) {
                uint32_t off = (uint32_t)(mb * 16 + lrow) * PITCHB +
                               (uint32_t)(ks * 16 + lcol) * 2;
                uint32_t Ah[4], Al[4];
                LDSM4(Ah, sbHi + off);
                LDSM4(Al, sbLo + off);
#pragma unroll
                for (int sl = 0; sl < 2; sl++) {
                    MMA16816(ahh[sl], Ah, Bh[ks][sl]);
                    MMA16816(ahl[sl], Ah, Bl[ks][sl]);
                    MMA16816(alh[sl], Al, Bh[ks][sl]);
                }
            }
            int row0 = mb * 16 + g;
#pragma unroll
            for (int sl = 0; sl < 2; sl++) {
                int cb = warpN + sl * 8 + tid4 * 2;
                float2 v0, v1;
                v0.x = ahh[sl][0] + ahl[sl][0] + alh[sl][0];
                v0.y = ahh[sl][1] + ahl[sl][1] + alh[sl][1];
                v1.x = ahh[sl][2] + ahl[sl][2] + alh[sl][2];
                v1.y = ahh[sl][3] + ahl[sl][3] + alh[sl][3];
                __stcs((float2*)(yt + (size_t)row0 * DIM + cb), v0);
                __stcs((float2*)(yt + (size_t)(row0 + 8) * DIM + cb), v1);
            }
        }

        tile = next;
        if (tile >= NTILES) break;
    }
}

// ---------------------------------------------------------------------------
// Launch
// ---------------------------------------------------------------------------
extern "C" void kernel_launch(void* const* d_in, const int* in_sizes, int n_in,
                              void* d_out, int out_size) {
    const float* x    = (const float*)d_in[0];   // [BATCH, DIM]
    const float* V    = (const float*)d_in[1];   // [DIM, DIM] (v_i = columns)
    const float* sc   = (const float*)d_in[2];   // [1]
    const float* diag = (const float*)d_in[3];   // [DIM]
    float* out = (float*)d_out;

    cudaFuncSetAttribute(build_w_kernel,
                         cudaFuncAttributeMaxDynamicSharedMemorySize, BW_SMEM);
    cudaFuncSetAttribute(gemm_kernel,
                         cudaFuncAttributeMaxDynamicSharedMemorySize, SMEM_BYTES);

    build_w_kernel<<<1, 256, BW_SMEM>>>(V, sc, diag, out, out_size);
    gemm_kernel<<<GRID, 256, SMEM_BYTES>>>(x, out);
}